// round 13
// baseline (speedup 1.0000x reference)
#include <cuda_runtime.h>
#include <cuda_fp16.h>
#include <cstdint>

#define GSZ     (48*48*48)        // 110592
#define TPB     64                // rows per block iteration (32 per half)
#define THREADS 512
#define NBLK    296
#define TILES_PER_B (GSZ/TPB)     // 1728
#define WST     36                // wbuf row stride (u32 / half2 units)
#define WBSZ    (32*WST)          // 1152 u32 per half-buffer

// smem float offsets
#define OFF_BH2 0                 // ulonglong2[4][16][32] = 8192 floats
#define OFF_WB  8192              // 4 buffers (half x parity) x 1152 u32
#define OFF_RED 12800             // half x parity x 8 warps x 32 = 1024
#define OFF_B1  13824
#define OFF_W2  13952
#define OFF_NEG 14080             // negx[64], negy[64], negz[64]
#define OFF_ORG 14272
#define OFF_STP 14276
#define SMEM_BYTES (14336 * 4)    // 57344 B -> 2 blocks/SM

typedef unsigned long long u64;

__device__ float FWg[4 * 64 * 128];

template <int N> struct IC { static constexpr int value = N; };

// ---- helpers ----
__device__ __forceinline__ unsigned smem_u32(const void* p) {
    unsigned a;
    asm("{ .reg .u64 t; cvta.to.shared.u64 t, %1; cvt.u32.u64 %0, t; }" : "=r"(a) : "l"(p));
    return a;
}
__device__ __forceinline__ u64 dup2(float f) {
    u64 r; asm("mov.b64 %0, {%1, %1};" : "=l"(r) : "f"(f)); return r;
}
__device__ __forceinline__ u64 add2(u64 a, u64 b) {
    u64 r; asm("add.rn.f32x2 %0, %1, %2;" : "=l"(r) : "l"(a), "l"(b)); return r;
}
__device__ __forceinline__ u64 fma2v(u64 a, u64 b, u64 c) {
    u64 r; asm("fma.rn.f32x2 %0, %1, %2, %3;" : "=l"(r) : "l"(a), "l"(b), "l"(c)); return r;
}
__device__ __forceinline__ float2 unpk(u64 v) {
    float2 r; asm("mov.b64 {%0, %1}, %2;" : "=f"(r.x), "=f"(r.y) : "l"(v)); return r;
}
__device__ __forceinline__ void mma16816(float c[4], const unsigned a[4],
                                         unsigned b0, unsigned b1) {
    asm volatile(
        "mma.sync.aligned.m16n8k16.row.col.f32.f16.f16.f32 "
        "{%0,%1,%2,%3}, {%4,%5,%6,%7}, {%8,%9}, {%0,%1,%2,%3};"
        : "+f"(c[0]), "+f"(c[1]), "+f"(c[2]), "+f"(c[3])
        : "r"(a[0]), "r"(a[1]), "r"(a[2]), "r"(a[3]), "r"(b0), "r"(b1));
}
__device__ __forceinline__ void mma1688(float c[4], unsigned a0, unsigned a1,
                                        unsigned b0) {
    asm volatile(
        "mma.sync.aligned.m16n8k8.row.col.f32.f16.f16.f32 "
        "{%0,%1,%2,%3}, {%4,%5}, {%6}, {%0,%1,%2,%3};"
        : "+f"(c[0]), "+f"(c[1]), "+f"(c[2]), "+f"(c[3])
        : "r"(a0), "r"(a1), "r"(b0));
}
__device__ __forceinline__ void ldmA4(unsigned a[4], unsigned addr) {
    asm volatile("ldmatrix.sync.aligned.m8n8.x4.shared.b16 {%0,%1,%2,%3}, [%4];"
        : "=r"(a[0]), "=r"(a[1]), "=r"(a[2]), "=r"(a[3]) : "r"(addr));
}
__device__ __forceinline__ void ldmA2(unsigned &a0, unsigned &a1, unsigned addr) {
    asm volatile("ldmatrix.sync.aligned.m8n8.x2.shared.b16 {%0,%1}, [%2];"
        : "=r"(a0), "=r"(a1) : "r"(addr));
}
__device__ __forceinline__ void hbar(int id) {
    asm volatile("bar.sync %0, 256;" :: "r"(id) : "memory");
}

// ---------------- prep: FW[b][n][j] = sum_e F[b][n][e] * W1[e][j] ----------
__global__ void __launch_bounds__(128, 8)
prep_kernel(const float* __restrict__ feat, const float* __restrict__ W1)
{
    __shared__ float frow[128];
    const int row = blockIdx.x;            // b*64+n
    const int j   = threadIdx.x;
    frow[j] = feat[row * 128 + j];
    __syncthreads();
    float a0 = 0.f, a1 = 0.f, a2 = 0.f, a3 = 0.f;
    #pragma unroll 8
    for (int e = 0; e < 128; e += 4) {
        a0 += frow[e]     * __ldg(W1 + (e)     * 128 + j);
        a1 += frow[e + 1] * __ldg(W1 + (e + 1) * 128 + j);
        a2 += frow[e + 2] * __ldg(W1 + (e + 2) * 128 + j);
        a3 += frow[e + 3] * __ldg(W1 + (e + 3) * 128 + j);
    }
    FWg[row * 128 + j] = (a0 + a1) + (a2 + a3);
}

// ---------------- main ------------------------------------------------------
__global__ void __launch_bounds__(THREADS, 2)
dgnn13_kernel(const float* __restrict__ pos,
              const float* __restrict__ feat,
              const float* __restrict__ origin,
              const float* __restrict__ lattice,
              const float* __restrict__ scale_p,
              const float* __restrict__ b1,
              const float* __restrict__ W2,
              const float* __restrict__ b2_p,
              const int*   __restrict__ bnodes,
              float* __restrict__ out,
              float* __restrict__ cout)
{
    extern __shared__ float sm[];
    ulonglong2* BH2 = (ulonglong2*)(sm + OFF_BH2);
    float* red  = sm + OFF_RED;
    float* b1s  = sm + OFF_B1;
    float* W2s  = sm + OFF_W2;
    float* negx = sm + OFF_NEG;
    float* negy = negx + 64;
    float* negz = negy + 64;
    float* orgb = sm + OFF_ORG;
    float* stpb = sm + OFF_STP;

    const int tid  = threadIdx.x;
    const int lane = tid & 31;
    const int half = tid >> 8;
    const int htid = tid & 255;
    const int w    = htid >> 5;        // warp in half: 0..7, owns x-pair w + h-pair 8+w
    const unsigned smb = smem_u32(sm);

    unsigned* wbh[2] = {
        (unsigned*)(sm + OFF_WB) + (half * 2 + 0) * WBSZ,
        (unsigned*)(sm + OFF_WB) + (half * 2 + 1) * WBSZ };
    const unsigned wbu[2] = {
        smb + (OFF_WB + (half * 2 + 0) * WBSZ) * 4u,
        smb + (OFF_WB + (half * 2 + 1) * WBSZ) * 4u };

    // ---- block -> batch allocation ----
    int bn4[4], wgt[4], wsum = 0;
    #pragma unroll
    for (int i = 0; i < 4; i++) {
        bn4[i] = bnodes[i];
        const int rem = bn4[i] & 15;
        const int kf  = (bn4[i] >> 4) + (rem > 8 ? 1 : 0);
        const int tl  = (rem >= 1 && rem <= 8) ? 1 : 0;
        wgt[i] = 2 * kf + tl + 4;
        wsum  += wgt[i];
    }
    int bnd[5]; bnd[0] = 0;
    { int cum = 0;
      #pragma unroll
      for (int i = 0; i < 4; i++) { cum += wgt[i];
          bnd[i + 1] = (2 * NBLK * cum + wsum) / (2 * wsum); } }
    int b = 0;
    while (b < 3 && (int)blockIdx.x >= bnd[b + 1]) b++;
    const int rank = blockIdx.x - bnd[b];
    const int nblk = bnd[b + 1] - bnd[b];
    const int bn   = bn4[b];
    const int rem  = bn & 15;
    const int kF   = (bn >> 4) + (rem > 8 ? 1 : 0);
    const int tail = (rem >= 1 && rem <= 8) ? 1 : 0;

    // ---- prologue (block-wide) ----
    if (tid < 128) { b1s[tid] = b1[tid]; W2s[tid] = W2[tid]; }
    if (tid < 192) {
        const int n  = tid & 63;
        const int ax = tid >> 6;
        const float p = pos[b * 192 + n * 3 + ax];
        sm[OFF_NEG + ax * 64 + n] = (n < bn) ? -p : (ax == 0 ? -1.0e19f : 0.0f);
    }
    if (tid < 3) {
        orgb[tid] = origin[b * 3 + tid];
        stpb[tid] = lattice[b * 9 + tid * 4] * (1.0f / 47.0f);
    }
    const float s   = scale_p[0];
    const float b2v = b2_p[0];
    const u64 s2d   = dup2(s * s);

    // B fragments (fp16, col-permuted, 2 ct packed per ulonglong2)
    for (int task = tid; task < 2048; task += THREADS) {
        const int ln   = task & 31;
        const int pair = (task >> 5) & 15;
        const int ks   = task >> 9;
        const int p    = ln >> 2;
        const int lcol0 = pair * 16 + 4 * (p >> 1) + (p & 1);
        const int k0   = ks * 16 + (ln & 3) * 2;
        ulonglong2 v;
        #pragma unroll
        for (int o = 0; o < 2; o++) {
            const int col = lcol0 + 2 * o;
            const float* src = (col < 128)
                ? (feat + (size_t)b * 8192 + col)
                : (FWg + (size_t)b * 8192 + (col - 128));
            __half2 h0 = __floats2half2_rn(__ldg(src + (size_t)k0 * 128),
                                           __ldg(src + (size_t)(k0 + 1) * 128));
            __half2 h1 = __floats2half2_rn(__ldg(src + (size_t)(k0 + 8) * 128),
                                           __ldg(src + (size_t)(k0 + 9) * 128));
            u64 u = (u64)(*(unsigned*)&h0) | ((u64)(*(unsigned*)&h1) << 32);
            if (o == 0) v.x = u; else v.y = u;
        }
        BH2[(ks * 16 + pair) * 32 + ln] = v;
    }

    const int q   = lane & 3;
    const int rr  = lane >> 2;
    const int barid = 1 + half;

    const int t_ph1 = htid & 31;
    const int slab  = (htid >> 5) << 3;

    auto phase1 = [&](int g0h, unsigned* dst) {
        const int g  = g0h + t_ph1;
        const int ix = g / 2304;
        const int rm = g - ix * 2304;
        const int iy = rm / 48;
        const int iz = rm - iy * 48;
        const u64 gxd = dup2(orgb[0] + (float)ix * stpb[0]);
        const u64 gyd = dup2(orgb[1] + (float)iy * stpb[1]);
        const u64 gzd = dup2(orgb[2] + (float)iz * stpb[2]);
        unsigned pk[4];
        #pragma unroll
        for (int p = 0; p < 4; p++) {
            const int n0 = slab + 2 * p;
            const u64 dx = add2(gxd, *(const u64*)&negx[n0]);
            const u64 dy = add2(gyd, *(const u64*)&negy[n0]);
            const u64 dz = add2(gzd, *(const u64*)&negz[n0]);
            u64 d2 = fma2v(dx, dx, s2d);
            d2 = fma2v(dy, dy, d2);
            d2 = fma2v(dz, dz, d2);
            const float2 f = unpk(d2);
            const float w0 = __fdividef(s, f.x);   // masked atoms -> fp16 0
            const float w1 = __fdividef(s, f.y);
            __half2 hw = __floats2half2_rn(w0, w1);
            pk[p] = *(unsigned*)&hw;
        }
        *(uint4*)&dst[t_ph1 * WST + (slab >> 1)] =
            make_uint4(pk[0], pk[1], pk[2], pk[3]);
    };

    __syncthreads();                   // BH2 + constants ready (once)

    auto tile_loop = [&](auto KFC, auto TLC) {
        constexpr int KF   = decltype(KFC)::value;
        constexpr int TAIL = decltype(TLC)::value;
        constexpr int NA8  = KF * 16 + TAIL * 8;
        const bool ph1_on  = slab < NA8;

        const int tile0 = rank;
        if (ph1_on) phase1(tile0 * TPB + half * 32, wbh[0]);
        hbar(barid);

        int cur = 0;
        for (int tile = tile0; tile < TILES_PER_B; tile += nblk, cur ^= 1) {
            const int g0h = tile * TPB + half * 32;

            const int ntile = tile + nblk;
            if (ntile < TILES_PER_B && ph1_on)
                phase1(ntile * TPB + half * 32, wbh[cur ^ 1]);

            // c[mt][0..1] = x cols (pair w), c[mt][2..3] = h cols (pair 8+w)
            float c[2][4][4];
            #pragma unroll
            for (int mt = 0; mt < 2; mt++)
                #pragma unroll
                for (int ct = 0; ct < 4; ct++)
                    #pragma unroll
                    for (int r = 0; r < 4; r++) c[mt][ct][r] = 0.f;

            #pragma unroll
            for (int ks = 0; ks < KF; ks++) {
                unsigned a0[4], a1[4];
                const unsigned abase = wbu[cur] +
                    ((unsigned)((lane & 15) * WST + ks * 8 + (lane >> 4) * 4)) * 4u;
                ldmA4(a0, abase);
                ldmA4(a1, abase + 16 * WST * 4);
                const ulonglong2 bx = BH2[(ks * 16 + w) * 32 + lane];
                const ulonglong2 bh = BH2[(ks * 16 + 8 + w) * 32 + lane];
                mma16816(c[0][0], a0, (unsigned)bx.x, (unsigned)(bx.x >> 32));
                mma16816(c[0][1], a0, (unsigned)bx.y, (unsigned)(bx.y >> 32));
                mma16816(c[1][0], a1, (unsigned)bx.x, (unsigned)(bx.x >> 32));
                mma16816(c[1][1], a1, (unsigned)bx.y, (unsigned)(bx.y >> 32));
                mma16816(c[0][2], a0, (unsigned)bh.x, (unsigned)(bh.x >> 32));
                mma16816(c[0][3], a0, (unsigned)bh.y, (unsigned)(bh.y >> 32));
                mma16816(c[1][2], a1, (unsigned)bh.x, (unsigned)(bh.x >> 32));
                mma16816(c[1][3], a1, (unsigned)bh.y, (unsigned)(bh.y >> 32));
            }
            if (TAIL) {
                unsigned p00, p01, p10, p11;
                const unsigned abase = wbu[cur] +
                    ((unsigned)((lane & 15) * WST + KF * 8)) * 4u;
                ldmA2(p00, p01, abase);
                ldmA2(p10, p11, abase + 16 * WST * 4);
                const ulonglong2 bx = BH2[(KF * 16 + w) * 32 + lane];
                const ulonglong2 bh = BH2[(KF * 16 + 8 + w) * 32 + lane];
                mma1688(c[0][0], p00, p01, (unsigned)bx.x);
                mma1688(c[0][1], p00, p01, (unsigned)bx.y);
                mma1688(c[1][0], p10, p11, (unsigned)bx.x);
                mma1688(c[1][1], p10, p11, (unsigned)bx.y);
                mma1688(c[0][2], p00, p01, (unsigned)bh.x);
                mma1688(c[0][3], p00, p01, (unsigned)bh.y);
                mma1688(c[1][2], p10, p11, (unsigned)bh.x);
                mma1688(c[1][3], p10, p11, (unsigned)bh.y);
            }

            // ===== epilogue: h first (red path), then x stores =====
            {
                const int jb = w * 16 + 4 * q;
                const float4 bbv = *(const float4*)&b1s[jb];
                const float4 wwv = *(const float4*)&W2s[jb];
                #pragma unroll
                for (int mt = 0; mt < 2; mt++) {
                    float v0 = fmaxf(c[mt][2][0] + bbv.x, 0.f) * wwv.x
                             + fmaxf(c[mt][2][1] + bbv.y, 0.f) * wwv.y
                             + fmaxf(c[mt][3][0] + bbv.z, 0.f) * wwv.z
                             + fmaxf(c[mt][3][1] + bbv.w, 0.f) * wwv.w;
                    float v1 = fmaxf(c[mt][2][2] + bbv.x, 0.f) * wwv.x
                             + fmaxf(c[mt][2][3] + bbv.y, 0.f) * wwv.y
                             + fmaxf(c[mt][3][2] + bbv.z, 0.f) * wwv.z
                             + fmaxf(c[mt][3][3] + bbv.w, 0.f) * wwv.w;
                    v0 += __shfl_xor_sync(0xffffffffu, v0, 1);
                    v0 += __shfl_xor_sync(0xffffffffu, v0, 2);
                    v1 += __shfl_xor_sync(0xffffffffu, v1, 1);
                    v1 += __shfl_xor_sync(0xffffffffu, v1, 2);
                    if (q == 0) {
                        float* rd = red + ((half * 2 + cur) * 8 + w) * 32 + mt * 16;
                        rd[rr]     = v0;
                        rd[rr + 8] = v1;
                    }
                }
            }
            {
                const size_t base = ((size_t)b * GSZ + g0h) * 128;
                const int e0 = w * 16 + 4 * q;
                #pragma unroll
                for (int mt = 0; mt < 2; mt++) {
                    const int row0 = mt * 16 + rr;
                    float4 v0 = make_float4(c[mt][0][0], c[mt][0][1],
                                            c[mt][1][0], c[mt][1][1]);
                    float4 v1 = make_float4(c[mt][0][2], c[mt][0][3],
                                            c[mt][1][2], c[mt][1][3]);
                    __stcs((float4*)&cout[base + (size_t)row0 * 128 + e0], v0);
                    __stcs((float4*)&cout[base + (size_t)(row0 + 8) * 128 + e0], v1);
                }
            }
            hbar(barid);

            if (htid < 32) {
                const float* rd = red + (half * 2 + cur) * 256;
                float acc = b2v;
                #pragma unroll
                for (int ww = 0; ww < 8; ww++) acc += rd[ww * 32 + htid];
                __stcs(&out[(size_t)b * GSZ + g0h + htid], acc);
            }
        }
    };

    switch (kF * 2 + tail) {
        case 1: tile_loop(IC<0>{}, IC<1>{}); break;
        case 2: tile_loop(IC<1>{}, IC<0>{}); break;
        case 3: tile_loop(IC<1>{}, IC<1>{}); break;
        case 4: tile_loop(IC<2>{}, IC<0>{}); break;
        case 5: tile_loop(IC<2>{}, IC<1>{}); break;
        case 6: tile_loop(IC<3>{}, IC<0>{}); break;
        case 7: tile_loop(IC<3>{}, IC<1>{}); break;
        default: tile_loop(IC<4>{}, IC<0>{}); break;
    }
}

extern "C" void kernel_launch(void* const* d_in, const int* in_sizes, int n_in,
                              void* d_out, int out_size)
{
    const float* pos     = (const float*)d_in[0];
    const float* feat    = (const float*)d_in[1];
    const float* origin  = (const float*)d_in[2];
    const float* lattice = (const float*)d_in[3];
    const float* scale   = (const float*)d_in[4];
    const float* W1      = (const float*)d_in[5];
    const float* b1      = (const float*)d_in[6];
    const float* W2      = (const float*)d_in[7];
    const float* b2      = (const float*)d_in[8];
    const int*   bn      = (const int*)  d_in[9];

    float* out  = (float*)d_out;                 // [B,48,48,48]
    float* cout = out + (size_t)4 * GSZ;         // [B,48,48,48,128]

    prep_kernel<<<256, 128>>>(feat, W1);

    cudaFuncSetAttribute(dgnn13_kernel,
                         cudaFuncAttributeMaxDynamicSharedMemorySize, SMEM_BYTES);
    dgnn13_kernel<<<NBLK, THREADS, SMEM_BYTES>>>(
        pos, feat, origin, lattice, scale, b1, W2, b2, bn, out, cout);
}

// round 14
// speedup vs baseline: 1.1012x; 1.1012x over previous
#include <cuda_runtime.h>
#include <cuda_fp16.h>
#include <cstdint>

#define GSZ     (48*48*48)        // 110592
#define TPB     32                // rows per block tile
#define THREADS 256
#define NBLK    444               // 3 per SM
#define TILES_PER_B (GSZ/TPB)     // 3456
#define WST     36                // wbuf row stride (u32 / half2 units)
#define WBSZ    (32*WST)          // 1152 u32 per buffer

// smem float offsets
#define OFF_BH2 0                 // ulonglong2[4][16][32] = 8192 floats
#define OFF_WB  8192              // 2 parity x 1152 u32 = 2304
#define OFF_RED 10496             // 2 parity x 4 x 32 = 256
#define OFF_B1  10752
#define OFF_W2  10880
#define OFF_NEG 11008             // negx/negy/negz[64]
#define OFF_ORG 11200
#define OFF_STP 11204
#define SMEM_BYTES (11264 * 4)    // 45056 B -> 3 blocks/SM

typedef unsigned long long u64;

__device__ float FWg[4 * 64 * 128];

template <int N> struct IC { static constexpr int value = N; };

// ---- helpers ----
__device__ __forceinline__ unsigned smem_u32(const void* p) {
    unsigned a;
    asm("{ .reg .u64 t; cvta.to.shared.u64 t, %1; cvt.u32.u64 %0, t; }" : "=r"(a) : "l"(p));
    return a;
}
__device__ __forceinline__ u64 dup2(float f) {
    u64 r; asm("mov.b64 %0, {%1, %1};" : "=l"(r) : "f"(f)); return r;
}
__device__ __forceinline__ u64 add2(u64 a, u64 b) {
    u64 r; asm("add.rn.f32x2 %0, %1, %2;" : "=l"(r) : "l"(a), "l"(b)); return r;
}
__device__ __forceinline__ u64 fma2v(u64 a, u64 b, u64 c) {
    u64 r; asm("fma.rn.f32x2 %0, %1, %2, %3;" : "=l"(r) : "l"(a), "l"(b), "l"(c)); return r;
}
__device__ __forceinline__ float2 unpk(u64 v) {
    float2 r; asm("mov.b64 {%0, %1}, %2;" : "=f"(r.x), "=f"(r.y) : "l"(v)); return r;
}
__device__ __forceinline__ void mma16816(float c[4], const unsigned a[4],
                                         unsigned b0, unsigned b1) {
    asm volatile(
        "mma.sync.aligned.m16n8k16.row.col.f32.f16.f16.f32 "
        "{%0,%1,%2,%3}, {%4,%5,%6,%7}, {%8,%9}, {%0,%1,%2,%3};"
        : "+f"(c[0]), "+f"(c[1]), "+f"(c[2]), "+f"(c[3])
        : "r"(a[0]), "r"(a[1]), "r"(a[2]), "r"(a[3]), "r"(b0), "r"(b1));
}
__device__ __forceinline__ void mma1688(float c[4], unsigned a0, unsigned a1,
                                        unsigned b0) {
    asm volatile(
        "mma.sync.aligned.m16n8k8.row.col.f32.f16.f16.f32 "
        "{%0,%1,%2,%3}, {%4,%5}, {%6}, {%0,%1,%2,%3};"
        : "+f"(c[0]), "+f"(c[1]), "+f"(c[2]), "+f"(c[3])
        : "r"(a0), "r"(a1), "r"(b0));
}
__device__ __forceinline__ void ldmA4(unsigned a[4], unsigned addr) {
    asm volatile("ldmatrix.sync.aligned.m8n8.x4.shared.b16 {%0,%1,%2,%3}, [%4];"
        : "=r"(a[0]), "=r"(a[1]), "=r"(a[2]), "=r"(a[3]) : "r"(addr));
}
__device__ __forceinline__ void ldmA2(unsigned &a0, unsigned &a1, unsigned addr) {
    asm volatile("ldmatrix.sync.aligned.m8n8.x2.shared.b16 {%0,%1}, [%2];"
        : "=r"(a0), "=r"(a1) : "r"(addr));
}

// ---------------- prep: FW[b][n][j] = sum_e F[b][n][e] * W1[e][j] ----------
__global__ void __launch_bounds__(128, 8)
prep_kernel(const float* __restrict__ feat, const float* __restrict__ W1)
{
    __shared__ float frow[128];
    const int row = blockIdx.x;            // b*64+n
    const int j   = threadIdx.x;
    frow[j] = feat[row * 128 + j];
    __syncthreads();
    float a0 = 0.f, a1 = 0.f, a2 = 0.f, a3 = 0.f;
    #pragma unroll 8
    for (int e = 0; e < 128; e += 4) {
        a0 += frow[e]     * __ldg(W1 + (e)     * 128 + j);
        a1 += frow[e + 1] * __ldg(W1 + (e + 1) * 128 + j);
        a2 += frow[e + 2] * __ldg(W1 + (e + 2) * 128 + j);
        a3 += frow[e + 3] * __ldg(W1 + (e + 3) * 128 + j);
    }
    FWg[row * 128 + j] = (a0 + a1) + (a2 + a3);
}

// ---------------- main ------------------------------------------------------
__global__ void __launch_bounds__(THREADS, 3)
dgnn14_kernel(const float* __restrict__ pos,
              const float* __restrict__ feat,
              const float* __restrict__ origin,
              const float* __restrict__ lattice,
              const float* __restrict__ scale_p,
              const float* __restrict__ b1,
              const float* __restrict__ W2,
              const float* __restrict__ b2_p,
              const int*   __restrict__ bnodes,
              float* __restrict__ out,
              float* __restrict__ cout)
{
    extern __shared__ float sm[];
    ulonglong2* BH2 = (ulonglong2*)(sm + OFF_BH2);
    float* red  = sm + OFF_RED;
    float* b1s  = sm + OFF_B1;
    float* W2s  = sm + OFF_W2;
    float* negx = sm + OFF_NEG;
    float* negy = negx + 64;
    float* negz = negy + 64;
    float* orgb = sm + OFF_ORG;
    float* stpb = sm + OFF_STP;

    const int tid  = threadIdx.x;
    const int lane = tid & 31;
    const int cg   = tid >> 5;         // warp 0..7: 0-3 x cols, 4-7 h cols
    const unsigned smb = smem_u32(sm);

    unsigned* wbh[2] = {
        (unsigned*)(sm + OFF_WB),
        (unsigned*)(sm + OFF_WB) + WBSZ };
    const unsigned wbu[2] = {
        smb + OFF_WB * 4u,
        smb + (OFF_WB + WBSZ) * 4u };

    // ---- block -> batch allocation ----
    int bn4[4], wgt[4], wsum = 0;
    #pragma unroll
    for (int i = 0; i < 4; i++) {
        bn4[i] = bnodes[i];
        const int rem = bn4[i] & 15;
        const int kf  = (bn4[i] >> 4) + (rem > 8 ? 1 : 0);
        const int tl  = (rem >= 1 && rem <= 8) ? 1 : 0;
        wgt[i] = 2 * kf + tl + 4;
        wsum  += wgt[i];
    }
    int bnd[5]; bnd[0] = 0;
    { int cum = 0;
      #pragma unroll
      for (int i = 0; i < 4; i++) { cum += wgt[i];
          bnd[i + 1] = (2 * NBLK * cum + wsum) / (2 * wsum); } }
    int b = 0;
    while (b < 3 && (int)blockIdx.x >= bnd[b + 1]) b++;
    const int rank = blockIdx.x - bnd[b];
    const int nblk = bnd[b + 1] - bnd[b];
    const int bn   = bn4[b];
    const int rem  = bn & 15;
    const int kF   = (bn >> 4) + (rem > 8 ? 1 : 0);
    const int tail = (rem >= 1 && rem <= 8) ? 1 : 0;

    // ---- prologue ----
    if (tid < 128) { b1s[tid] = b1[tid]; W2s[tid] = W2[tid]; }
    if (tid < 192) {
        const int n  = tid & 63;
        const int ax = tid >> 6;
        const float p = pos[b * 192 + n * 3 + ax];
        sm[OFF_NEG + ax * 64 + n] = (n < bn) ? -p : (ax == 0 ? -1.0e19f : 0.0f);
    }
    if (tid < 3) {
        orgb[tid] = origin[b * 3 + tid];
        stpb[tid] = lattice[b * 9 + tid * 4] * (1.0f / 47.0f);
    }
    const float s   = scale_p[0];
    const float b2v = b2_p[0];
    const u64 s2d   = dup2(s * s);

    // B fragments (fp16, col-permuted, 2 ct packed per ulonglong2)
    for (int task = tid; task < 2048; task += THREADS) {
        const int ln   = task & 31;
        const int pair = (task >> 5) & 15;
        const int ks   = task >> 9;
        const int p    = ln >> 2;
        const int lcol0 = pair * 16 + 4 * (p >> 1) + (p & 1);
        const int k0   = ks * 16 + (ln & 3) * 2;
        ulonglong2 v;
        #pragma unroll
        for (int o = 0; o < 2; o++) {
            const int col = lcol0 + 2 * o;
            const float* src = (col < 128)
                ? (feat + (size_t)b * 8192 + col)
                : (FWg + (size_t)b * 8192 + (col - 128));
            __half2 h0 = __floats2half2_rn(__ldg(src + (size_t)k0 * 128),
                                           __ldg(src + (size_t)(k0 + 1) * 128));
            __half2 h1 = __floats2half2_rn(__ldg(src + (size_t)(k0 + 8) * 128),
                                           __ldg(src + (size_t)(k0 + 9) * 128));
            u64 u = (u64)(*(unsigned*)&h0) | ((u64)(*(unsigned*)&h1) << 32);
            if (o == 0) v.x = u; else v.y = u;
        }
        BH2[(ks * 16 + pair) * 32 + ln] = v;
    }

    const int q   = lane & 3;
    const int rr  = lane >> 5 ? 0 : (lane >> 2);   // lane>>2, 0..7

    const int t_ph1 = tid & 31;
    const int slab  = (tid >> 5) << 3;

    auto phase1 = [&](int g0h, unsigned* dst) {
        const int g  = g0h + t_ph1;
        const int ix = g / 2304;
        const int rm = g - ix * 2304;
        const int iy = rm / 48;
        const int iz = rm - iy * 48;
        const u64 gxd = dup2(orgb[0] + (float)ix * stpb[0]);
        const u64 gyd = dup2(orgb[1] + (float)iy * stpb[1]);
        const u64 gzd = dup2(orgb[2] + (float)iz * stpb[2]);
        unsigned pk[4];
        #pragma unroll
        for (int p = 0; p < 4; p++) {
            const int n0 = slab + 2 * p;
            const u64 dx = add2(gxd, *(const u64*)&negx[n0]);
            const u64 dy = add2(gyd, *(const u64*)&negy[n0]);
            const u64 dz = add2(gzd, *(const u64*)&negz[n0]);
            u64 d2 = fma2v(dx, dx, s2d);
            d2 = fma2v(dy, dy, d2);
            d2 = fma2v(dz, dz, d2);
            const float2 f = unpk(d2);
            const float w0 = __fdividef(s, f.x);   // masked atoms -> fp16 0
            const float w1 = __fdividef(s, f.y);
            __half2 hw = __floats2half2_rn(w0, w1);
            pk[p] = *(unsigned*)&hw;
        }
        *(uint4*)&dst[t_ph1 * WST + (slab >> 1)] =
            make_uint4(pk[0], pk[1], pk[2], pk[3]);
    };

    __syncthreads();                   // BH2 + constants ready

    auto tile_loop = [&](auto KFC, auto TLC) {
        constexpr int KF   = decltype(KFC)::value;
        constexpr int TAIL = decltype(TLC)::value;
        constexpr int NA8  = KF * 16 + TAIL * 8;
        const bool ph1_on  = slab < NA8;

        const int tile0 = rank;
        if (ph1_on) phase1(tile0 * TPB, wbh[0]);
        __syncthreads();

        int cur = 0;
        for (int tile = tile0; tile < TILES_PER_B; tile += nblk, cur ^= 1) {
            const int g0h = tile * TPB;

            const int ntile = tile + nblk;
            if (ntile < TILES_PER_B && ph1_on)
                phase1(ntile * TPB, wbh[cur ^ 1]);

            float c[2][4][4];
            #pragma unroll
            for (int mt = 0; mt < 2; mt++)
                #pragma unroll
                for (int ct = 0; ct < 4; ct++)
                    #pragma unroll
                    for (int r = 0; r < 4; r++) c[mt][ct][r] = 0.f;

            #pragma unroll
            for (int ks = 0; ks < KF; ks++) {
                unsigned a0[4], a1[4];
                const unsigned abase = wbu[cur] +
                    ((unsigned)((lane & 15) * WST + ks * 8 + (lane >> 4) * 4)) * 4u;
                ldmA4(a0, abase);
                ldmA4(a1, abase + 16 * WST * 4);
                #pragma unroll
                for (int cp = 0; cp < 2; cp++) {
                    const ulonglong2 bb = BH2[(ks * 16 + cg * 2 + cp) * 32 + lane];
                    const unsigned bx0 = (unsigned)bb.x, bx1 = (unsigned)(bb.x >> 32);
                    const unsigned by0 = (unsigned)bb.y, by1 = (unsigned)(bb.y >> 32);
                    mma16816(c[0][2 * cp],     a0, bx0, bx1);
                    mma16816(c[0][2 * cp + 1], a0, by0, by1);
                    mma16816(c[1][2 * cp],     a1, bx0, bx1);
                    mma16816(c[1][2 * cp + 1], a1, by0, by1);
                }
            }
            if (TAIL) {
                unsigned p00, p01, p10, p11;
                const unsigned abase = wbu[cur] +
                    ((unsigned)((lane & 15) * WST + KF * 8)) * 4u;
                ldmA2(p00, p01, abase);
                ldmA2(p10, p11, abase + 16 * WST * 4);
                #pragma unroll
                for (int cp = 0; cp < 2; cp++) {
                    const ulonglong2 bb = BH2[(KF * 16 + cg * 2 + cp) * 32 + lane];
                    mma1688(c[0][2 * cp],     p00, p01, (unsigned)bb.x);
                    mma1688(c[0][2 * cp + 1], p00, p01, (unsigned)bb.y);
                    mma1688(c[1][2 * cp],     p10, p11, (unsigned)bb.x);
                    mma1688(c[1][2 * cp + 1], p10, p11, (unsigned)bb.y);
                }
            }

            // ===== epilogue =====
            if (cg < 4) {
                const size_t base = ((size_t)b * GSZ + g0h) * 128;
                #pragma unroll
                for (int mt = 0; mt < 2; mt++) {
                    const int row0 = mt * 16 + (lane >> 2);
                    #pragma unroll
                    for (int i = 0; i < 2; i++) {
                        const int e0 = cg * 32 + 16 * i + 4 * q;
                        float4 v0 = make_float4(c[mt][2*i][0], c[mt][2*i][1],
                                                c[mt][2*i+1][0], c[mt][2*i+1][1]);
                        float4 v1 = make_float4(c[mt][2*i][2], c[mt][2*i][3],
                                                c[mt][2*i+1][2], c[mt][2*i+1][3]);
                        __stcs((float4*)&cout[base + (size_t)row0 * 128 + e0], v0);
                        __stcs((float4*)&cout[base + (size_t)(row0 + 8) * 128 + e0], v1);
                    }
                }
            } else {
                const int cgh = cg - 4;
                #pragma unroll
                for (int mt = 0; mt < 2; mt++) {
                    float v0 = 0.f, v1 = 0.f;
                    #pragma unroll
                    for (int i = 0; i < 2; i++) {
                        const int jb = cgh * 32 + 16 * i + 4 * q;
                        const float4 bbv = *(const float4*)&b1s[jb];
                        const float4 wwv = *(const float4*)&W2s[jb];
                        v0 += fmaxf(c[mt][2*i][0]   + bbv.x, 0.f) * wwv.x
                            + fmaxf(c[mt][2*i][1]   + bbv.y, 0.f) * wwv.y
                            + fmaxf(c[mt][2*i+1][0] + bbv.z, 0.f) * wwv.z
                            + fmaxf(c[mt][2*i+1][1] + bbv.w, 0.f) * wwv.w;
                        v1 += fmaxf(c[mt][2*i][2]   + bbv.x, 0.f) * wwv.x
                            + fmaxf(c[mt][2*i][3]   + bbv.y, 0.f) * wwv.y
                            + fmaxf(c[mt][2*i+1][2] + bbv.z, 0.f) * wwv.z
                            + fmaxf(c[mt][2*i+1][3] + bbv.w, 0.f) * wwv.w;
                    }
                    v0 += __shfl_xor_sync(0xffffffffu, v0, 1);
                    v0 += __shfl_xor_sync(0xffffffffu, v0, 2);
                    v1 += __shfl_xor_sync(0xffffffffu, v1, 1);
                    v1 += __shfl_xor_sync(0xffffffffu, v1, 2);
                    if (q == 0) {
                        float* rd = red + (cur * 4 + cgh) * 32 + mt * 16;
                        rd[lane >> 2]       = v0;
                        rd[(lane >> 2) + 8] = v1;
                    }
                }
            }
            __syncthreads();           // wbuf swap + red[cur] ready

            if (tid < 32) {
                const float* rd = red + cur * 128;
                __stcs(&out[(size_t)b * GSZ + g0h + tid],
                       rd[tid] + rd[32 + tid] + rd[64 + tid] + rd[96 + tid] + b2v);
            }
        }
    };

    switch (kF * 2 + tail) {
        case 1: tile_loop(IC<0>{}, IC<1>{}); break;
        case 2: tile_loop(IC<1>{}, IC<0>{}); break;
        case 3: tile_loop(IC<1>{}, IC<1>{}); break;
        case 4: tile_loop(IC<2>{}, IC<0>{}); break;
        case 5: tile_loop(IC<2>{}, IC<1>{}); break;
        case 6: tile_loop(IC<3>{}, IC<0>{}); break;
        case 7: tile_loop(IC<3>{}, IC<1>{}); break;
        default: tile_loop(IC<4>{}, IC<0>{}); break;
    }
}

extern "C" void kernel_launch(void* const* d_in, const int* in_sizes, int n_in,
                              void* d_out, int out_size)
{
    const float* pos     = (const float*)d_in[0];
    const float* feat    = (const float*)d_in[1];
    const float* origin  = (const float*)d_in[2];
    const float* lattice = (const float*)d_in[3];
    const float* scale   = (const float*)d_in[4];
    const float* W1      = (const float*)d_in[5];
    const float* b1      = (const float*)d_in[6];
    const float* W2      = (const float*)d_in[7];
    const float* b2      = (const float*)d_in[8];
    const int*   bn      = (const int*)  d_in[9];

    float* out  = (float*)d_out;                 // [B,48,48,48]
    float* cout = out + (size_t)4 * GSZ;         // [B,48,48,48,128]

    prep_kernel<<<256, 128>>>(feat, W1);

    cudaFuncSetAttribute(dgnn14_kernel,
                         cudaFuncAttributeMaxDynamicSharedMemorySize, SMEM_BYTES);
    dgnn14_kernel<<<NBLK, THREADS, SMEM_BYTES>>>(
        pos, feat, origin, lattice, scale, b1, W2, b2, bn, out, cout);
}

// round 15
// speedup vs baseline: 1.2031x; 1.0925x over previous
#include <cuda_runtime.h>
#include <cuda_fp16.h>
#include <cstdint>

#define GSZ     (48*48*48)        // 110592
#define TPB     32                // rows per block tile
#define THREADS 256
#define NBLK    296               // 2 per SM
#define TILES_PER_B (GSZ/TPB)     // 3456
#define WST     36                // wbuf row stride (u32 / half2 units)
#define WBSZ    (32*WST)          // 1152 u32 per buffer

// smem float offsets
#define OFF_BH2 0                 // ulonglong2[4][16][32] = 8192 floats
#define OFF_WB  8192              // 2 parity x 1152 u32 = 2304
#define OFF_RED 10496             // 2 parity x 4 x 32 = 256
#define OFF_B1  10752
#define OFF_W2  10880
#define OFF_NEG 11008             // negx/negy/negz[64]
#define OFF_ORG 11200
#define OFF_STP 11204
#define SMEM_BYTES (11264 * 4)    // 45056 B

typedef unsigned long long u64;

__device__ float FWg[4 * 64 * 128];

template <int N> struct IC { static constexpr int value = N; };

// ---- helpers ----
__device__ __forceinline__ unsigned smem_u32(const void* p) {
    unsigned a;
    asm("{ .reg .u64 t; cvta.to.shared.u64 t, %1; cvt.u32.u64 %0, t; }" : "=r"(a) : "l"(p));
    return a;
}
__device__ __forceinline__ u64 dup2(float f) {
    u64 r; asm("mov.b64 %0, {%1, %1};" : "=l"(r) : "f"(f)); return r;
}
__device__ __forceinline__ u64 add2(u64 a, u64 b) {
    u64 r; asm("add.rn.f32x2 %0, %1, %2;" : "=l"(r) : "l"(a), "l"(b)); return r;
}
__device__ __forceinline__ u64 fma2v(u64 a, u64 b, u64 c) {
    u64 r; asm("fma.rn.f32x2 %0, %1, %2, %3;" : "=l"(r) : "l"(a), "l"(b), "l"(c)); return r;
}
__device__ __forceinline__ float2 unpk(u64 v) {
    float2 r; asm("mov.b64 {%0, %1}, %2;" : "=f"(r.x), "=f"(r.y) : "l"(v)); return r;
}
__device__ __forceinline__ void mma16816(float c[4], const unsigned a[4],
                                         unsigned b0, unsigned b1) {
    asm volatile(
        "mma.sync.aligned.m16n8k16.row.col.f32.f16.f16.f32 "
        "{%0,%1,%2,%3}, {%4,%5,%6,%7}, {%8,%9}, {%0,%1,%2,%3};"
        : "+f"(c[0]), "+f"(c[1]), "+f"(c[2]), "+f"(c[3])
        : "r"(a[0]), "r"(a[1]), "r"(a[2]), "r"(a[3]), "r"(b0), "r"(b1));
}
__device__ __forceinline__ void mma1688(float c[4], unsigned a0, unsigned a1,
                                        unsigned b0) {
    asm volatile(
        "mma.sync.aligned.m16n8k8.row.col.f32.f16.f16.f32 "
        "{%0,%1,%2,%3}, {%4,%5}, {%6}, {%0,%1,%2,%3};"
        : "+f"(c[0]), "+f"(c[1]), "+f"(c[2]), "+f"(c[3])
        : "r"(a0), "r"(a1), "r"(b0));
}
__device__ __forceinline__ void ldmA4(unsigned a[4], unsigned addr) {
    asm volatile("ldmatrix.sync.aligned.m8n8.x4.shared.b16 {%0,%1,%2,%3}, [%4];"
        : "=r"(a[0]), "=r"(a[1]), "=r"(a[2]), "=r"(a[3]) : "r"(addr));
}
__device__ __forceinline__ void ldmA2(unsigned &a0, unsigned &a1, unsigned addr) {
    asm volatile("ldmatrix.sync.aligned.m8n8.x2.shared.b16 {%0,%1}, [%2];"
        : "=r"(a0), "=r"(a1) : "r"(addr));
}

// ---------------- prep: FW[b][n][j] = sum_e F[b][n][e] * W1[e][j] ----------
__global__ void __launch_bounds__(128, 8)
prep_kernel(const float* __restrict__ feat, const float* __restrict__ W1)
{
    __shared__ float frow[128];
    const int row = blockIdx.x;            // b*64+n
    const int j   = threadIdx.x;
    frow[j] = feat[row * 128 + j];
    __syncthreads();
    float a0 = 0.f, a1 = 0.f, a2 = 0.f, a3 = 0.f;
    #pragma unroll 8
    for (int e = 0; e < 128; e += 4) {
        a0 += frow[e]     * __ldg(W1 + (e)     * 128 + j);
        a1 += frow[e + 1] * __ldg(W1 + (e + 1) * 128 + j);
        a2 += frow[e + 2] * __ldg(W1 + (e + 2) * 128 + j);
        a3 += frow[e + 3] * __ldg(W1 + (e + 3) * 128 + j);
    }
    FWg[row * 128 + j] = (a0 + a1) + (a2 + a3);
}

// ---------------- main ------------------------------------------------------
__global__ void __launch_bounds__(THREADS, 2)
dgnn15_kernel(const float* __restrict__ pos,
              const float* __restrict__ feat,
              const float* __restrict__ origin,
              const float* __restrict__ lattice,
              const float* __restrict__ scale_p,
              const float* __restrict__ b1,
              const float* __restrict__ W2,
              const float* __restrict__ b2_p,
              const int*   __restrict__ bnodes,
              float* __restrict__ out,
              float* __restrict__ cout)
{
    extern __shared__ float sm[];
    ulonglong2* BH2 = (ulonglong2*)(sm + OFF_BH2);
    float* red  = sm + OFF_RED;
    float* b1s  = sm + OFF_B1;
    float* W2s  = sm + OFF_W2;
    float* negx = sm + OFF_NEG;
    float* negy = negx + 64;
    float* negz = negy + 64;
    float* orgb = sm + OFF_ORG;
    float* stpb = sm + OFF_STP;

    const int tid  = threadIdx.x;
    const int lane = tid & 31;
    const int cg   = tid >> 5;         // warp 0..7: 0-3 x cols, 4-7 h cols
    const unsigned smb = smem_u32(sm);

    unsigned* wbh[2] = {
        (unsigned*)(sm + OFF_WB),
        (unsigned*)(sm + OFF_WB) + WBSZ };
    const unsigned wbu[2] = {
        smb + OFF_WB * 4u,
        smb + (OFF_WB + WBSZ) * 4u };

    // ---- block -> batch allocation ----
    int bn4[4], wgt[4], wsum = 0;
    #pragma unroll
    for (int i = 0; i < 4; i++) {
        bn4[i] = bnodes[i];
        const int rem = bn4[i] & 15;
        const int kf  = (bn4[i] >> 4) + (rem > 8 ? 1 : 0);
        const int tl  = (rem >= 1 && rem <= 8) ? 1 : 0;
        wgt[i] = 2 * kf + tl + 4;
        wsum  += wgt[i];
    }
    int bnd[5]; bnd[0] = 0;
    { int cum = 0;
      #pragma unroll
      for (int i = 0; i < 4; i++) { cum += wgt[i];
          bnd[i + 1] = (2 * NBLK * cum + wsum) / (2 * wsum); } }
    int b = 0;
    while (b < 3 && (int)blockIdx.x >= bnd[b + 1]) b++;
    const int rank = blockIdx.x - bnd[b];
    const int nblk = bnd[b + 1] - bnd[b];
    const int bn   = bn4[b];
    const int rem  = bn & 15;
    const int kF   = (bn >> 4) + (rem > 8 ? 1 : 0);
    const int tail = (rem >= 1 && rem <= 8) ? 1 : 0;

    // ---- prologue ----
    if (tid < 128) { b1s[tid] = b1[tid]; W2s[tid] = W2[tid]; }
    if (tid < 192) {
        const int n  = tid & 63;
        const int ax = tid >> 6;
        const float p = pos[b * 192 + n * 3 + ax];
        sm[OFF_NEG + ax * 64 + n] = (n < bn) ? -p : (ax == 0 ? -1.0e19f : 0.0f);
    }
    if (tid < 3) {
        orgb[tid] = origin[b * 3 + tid];
        stpb[tid] = lattice[b * 9 + tid * 4] * (1.0f / 47.0f);
    }
    const float s   = scale_p[0];
    const float b2v = b2_p[0];
    const u64 s2d   = dup2(s * s);

    // B fragments (fp16, col-permuted, 2 ct packed per ulonglong2)
    for (int task = tid; task < 2048; task += THREADS) {
        const int ln   = task & 31;
        const int pair = (task >> 5) & 15;
        const int ks   = task >> 9;
        const int p    = ln >> 2;
        const int lcol0 = pair * 16 + 4 * (p >> 1) + (p & 1);
        const int k0   = ks * 16 + (ln & 3) * 2;
        ulonglong2 v;
        #pragma unroll
        for (int o = 0; o < 2; o++) {
            const int col = lcol0 + 2 * o;
            const float* src = (col < 128)
                ? (feat + (size_t)b * 8192 + col)
                : (FWg + (size_t)b * 8192 + (col - 128));
            __half2 h0 = __floats2half2_rn(__ldg(src + (size_t)k0 * 128),
                                           __ldg(src + (size_t)(k0 + 1) * 128));
            __half2 h1 = __floats2half2_rn(__ldg(src + (size_t)(k0 + 8) * 128),
                                           __ldg(src + (size_t)(k0 + 9) * 128));
            u64 u = (u64)(*(unsigned*)&h0) | ((u64)(*(unsigned*)&h1) << 32);
            if (o == 0) v.x = u; else v.y = u;
        }
        BH2[(ks * 16 + pair) * 32 + ln] = v;
    }

    const int q = lane & 3;

    const int t_ph1 = tid & 31;
    const int slab  = (tid >> 5) << 3;

    auto phase1 = [&](int g0h, unsigned* dst) {
        const int g  = g0h + t_ph1;
        const int ix = g / 2304;
        const int rm = g - ix * 2304;
        const int iy = rm / 48;
        const int iz = rm - iy * 48;
        const u64 gxd = dup2(orgb[0] + (float)ix * stpb[0]);
        const u64 gyd = dup2(orgb[1] + (float)iy * stpb[1]);
        const u64 gzd = dup2(orgb[2] + (float)iz * stpb[2]);
        unsigned pk[4];
        #pragma unroll
        for (int p = 0; p < 4; p++) {
            const int n0 = slab + 2 * p;
            const u64 dx = add2(gxd, *(const u64*)&negx[n0]);
            const u64 dy = add2(gyd, *(const u64*)&negy[n0]);
            const u64 dz = add2(gzd, *(const u64*)&negz[n0]);
            u64 d2 = fma2v(dx, dx, s2d);
            d2 = fma2v(dy, dy, d2);
            d2 = fma2v(dz, dz, d2);
            const float2 f = unpk(d2);
            const float w0 = __fdividef(s, f.x);   // masked atoms -> fp16 0
            const float w1 = __fdividef(s, f.y);
            __half2 hw = __floats2half2_rn(w0, w1);
            pk[p] = *(unsigned*)&hw;
        }
        *(uint4*)&dst[t_ph1 * WST + (slab >> 1)] =
            make_uint4(pk[0], pk[1], pk[2], pk[3]);
    };

    __syncthreads();                   // BH2 + constants ready

    auto tile_loop = [&](auto KFC, auto TLC) {
        constexpr int KF   = decltype(KFC)::value;
        constexpr int TAIL = decltype(TLC)::value;
        constexpr int KT   = KF + TAIL;
        constexpr int NA8  = KF * 16 + TAIL * 8;
        const bool ph1_on  = slab < NA8;

        // ---- B resident in registers for the whole kernel ----
        ulonglong2 Bx[KT][2];
        #pragma unroll
        for (int ks = 0; ks < KT; ks++) {
            Bx[ks][0] = BH2[(ks * 16 + cg * 2 + 0) * 32 + lane];
            Bx[ks][1] = BH2[(ks * 16 + cg * 2 + 1) * 32 + lane];
        }

        const int tile0 = rank;
        if (ph1_on) phase1(tile0 * TPB, wbh[0]);
        __syncthreads();

        int cur = 0;
        for (int tile = tile0; tile < TILES_PER_B; tile += nblk, cur ^= 1) {
            const int g0h = tile * TPB;

            const int ntile = tile + nblk;
            if (ntile < TILES_PER_B && ph1_on)
                phase1(ntile * TPB, wbh[cur ^ 1]);

            float c[2][4][4];
            #pragma unroll
            for (int mt = 0; mt < 2; mt++)
                #pragma unroll
                for (int ct = 0; ct < 4; ct++)
                    #pragma unroll
                    for (int r = 0; r < 4; r++) c[mt][ct][r] = 0.f;

            #pragma unroll
            for (int ks = 0; ks < KF; ks++) {
                unsigned a0[4], a1[4];
                const unsigned abase = wbu[cur] +
                    ((unsigned)((lane & 15) * WST + ks * 8 + (lane >> 4) * 4)) * 4u;
                ldmA4(a0, abase);
                ldmA4(a1, abase + 16 * WST * 4);
                #pragma unroll
                for (int cp = 0; cp < 2; cp++) {
                    const ulonglong2 bb = Bx[ks][cp];
                    const unsigned bx0 = (unsigned)bb.x, bx1 = (unsigned)(bb.x >> 32);
                    const unsigned by0 = (unsigned)bb.y, by1 = (unsigned)(bb.y >> 32);
                    mma16816(c[0][2 * cp],     a0, bx0, bx1);
                    mma16816(c[0][2 * cp + 1], a0, by0, by1);
                    mma16816(c[1][2 * cp],     a1, bx0, bx1);
                    mma16816(c[1][2 * cp + 1], a1, by0, by1);
                }
            }
            if (TAIL) {
                unsigned p00, p01, p10, p11;
                const unsigned abase = wbu[cur] +
                    ((unsigned)((lane & 15) * WST + KF * 8)) * 4u;
                ldmA2(p00, p01, abase);
                ldmA2(p10, p11, abase + 16 * WST * 4);
                #pragma unroll
                for (int cp = 0; cp < 2; cp++) {
                    const ulonglong2 bb = Bx[KF][cp];
                    mma1688(c[0][2 * cp],     p00, p01, (unsigned)bb.x);
                    mma1688(c[0][2 * cp + 1], p00, p01, (unsigned)bb.y);
                    mma1688(c[1][2 * cp],     p10, p11, (unsigned)bb.x);
                    mma1688(c[1][2 * cp + 1], p10, p11, (unsigned)bb.y);
                }
            }

            // ===== epilogue =====
            if (cg < 4) {
                const size_t base = ((size_t)b * GSZ + g0h) * 128;
                #pragma unroll
                for (int mt = 0; mt < 2; mt++) {
                    const int row0 = mt * 16 + (lane >> 2);
                    #pragma unroll
                    for (int i = 0; i < 2; i++) {
                        const int e0 = cg * 32 + 16 * i + 4 * q;
                        float4 v0 = make_float4(c[mt][2*i][0], c[mt][2*i][1],
                                                c[mt][2*i+1][0], c[mt][2*i+1][1]);
                        float4 v1 = make_float4(c[mt][2*i][2], c[mt][2*i][3],
                                                c[mt][2*i+1][2], c[mt][2*i+1][3]);
                        __stcs((float4*)&cout[base + (size_t)row0 * 128 + e0], v0);
                        __stcs((float4*)&cout[base + (size_t)(row0 + 8) * 128 + e0], v1);
                    }
                }
            } else {
                const int cgh = cg - 4;
                #pragma unroll
                for (int mt = 0; mt < 2; mt++) {
                    float v0 = 0.f, v1 = 0.f;
                    #pragma unroll
                    for (int i = 0; i < 2; i++) {
                        const int jb = cgh * 32 + 16 * i + 4 * q;
                        const float4 bbv = *(const float4*)&b1s[jb];
                        const float4 wwv = *(const float4*)&W2s[jb];
                        v0 += fmaxf(c[mt][2*i][0]   + bbv.x, 0.f) * wwv.x
                            + fmaxf(c[mt][2*i][1]   + bbv.y, 0.f) * wwv.y
                            + fmaxf(c[mt][2*i+1][0] + bbv.z, 0.f) * wwv.z
                            + fmaxf(c[mt][2*i+1][1] + bbv.w, 0.f) * wwv.w;
                        v1 += fmaxf(c[mt][2*i][2]   + bbv.x, 0.f) * wwv.x
                            + fmaxf(c[mt][2*i][3]   + bbv.y, 0.f) * wwv.y
                            + fmaxf(c[mt][2*i+1][2] + bbv.z, 0.f) * wwv.z
                            + fmaxf(c[mt][2*i+1][3] + bbv.w, 0.f) * wwv.w;
                    }
                    v0 += __shfl_xor_sync(0xffffffffu, v0, 1);
                    v0 += __shfl_xor_sync(0xffffffffu, v0, 2);
                    v1 += __shfl_xor_sync(0xffffffffu, v1, 1);
                    v1 += __shfl_xor_sync(0xffffffffu, v1, 2);
                    if (q == 0) {
                        float* rd = red + (cur * 4 + cgh) * 32 + mt * 16;
                        rd[lane >> 2]       = v0;
                        rd[(lane >> 2) + 8] = v1;
                    }
                }
            }
            __syncthreads();           // wbuf swap + red[cur] ready

            if (tid < 32) {
                const float* rd = red + cur * 128;
                __stcs(&out[(size_t)b * GSZ + g0h + tid],
                       rd[tid] + rd[32 + tid] + rd[64 + tid] + rd[96 + tid] + b2v);
            }
        }
    };

    switch (kF * 2 + tail) {
        case 1: tile_loop(IC<0>{}, IC<1>{}); break;
        case 2: tile_loop(IC<1>{}, IC<0>{}); break;
        case 3: tile_loop(IC<1>{}, IC<1>{}); break;
        case 4: tile_loop(IC<2>{}, IC<0>{}); break;
        case 5: tile_loop(IC<2>{}, IC<1>{}); break;
        case 6: tile_loop(IC<3>{}, IC<0>{}); break;
        case 7: tile_loop(IC<3>{}, IC<1>{}); break;
        default: tile_loop(IC<4>{}, IC<0>{}); break;
    }
}

extern "C" void kernel_launch(void* const* d_in, const int* in_sizes, int n_in,
                              void* d_out, int out_size)
{
    const float* pos     = (const float*)d_in[0];
    const float* feat    = (const float*)d_in[1];
    const float* origin  = (const float*)d_in[2];
    const float* lattice = (const float*)d_in[3];
    const float* scale   = (const float*)d_in[4];
    const float* W1      = (const float*)d_in[5];
    const float* b1      = (const float*)d_in[6];
    const float* W2      = (const float*)d_in[7];
    const float* b2      = (const float*)d_in[8];
    const int*   bn      = (const int*)  d_in[9];

    float* out  = (float*)d_out;                 // [B,48,48,48]
    float* cout = out + (size_t)4 * GSZ;         // [B,48,48,48,128]

    prep_kernel<<<256, 128>>>(feat, W1);

    cudaFuncSetAttribute(dgnn15_kernel,
                         cudaFuncAttributeMaxDynamicSharedMemorySize, SMEM_BYTES);
    dgnn15_kernel<<<NBLK, THREADS, SMEM_BYTES>>>(
        pos, feat, origin, lattice, scale, b1, W2, b2, bn, out, cout);
}